// round 1
// baseline (speedup 1.0000x reference)
#include <cuda_runtime.h>
#include <cstdint>

// Problem constants (fixed by the reference: BATCH=4, SEQ=4096, DIM=1024)
#define B 4
#define L 4096
#define D 1024
#define NC 64          // number of chunks along L
#define C  64          // chunk length (NC * C == L)
#define LOG2C 6        // C = 2^6

// Scratch (allocation-free rule: __device__ globals)
__device__ float2 g_a[D];                 // decayed phazor a = p/|p| * exp(-|p|)
__device__ float2 g_aC[D];                // a^C
__device__ float2 g_totals[B * NC * D];   // per-chunk local scan totals (zero-init scan)
__device__ float2 g_carry[B * NC * D];    // carry-in h value for each chunk

__device__ __forceinline__ float2 cmul(float2 u, float2 v) {
    return make_float2(fmaf(u.x, v.x, -u.y * v.y), fmaf(u.x, v.y, u.y * v.x));
}

// K0: per-d precompute of a and a^C
__global__ void k_precompute(const float* __restrict__ pr, const float* __restrict__ pi) {
    int d = blockIdx.x * blockDim.x + threadIdx.x;
    if (d >= D) return;
    float r = pr[d], im = pi[d];
    float mag = sqrtf(fmaf(r, r, im * im));
    float s = __expf(-mag) / mag;
    float2 a = make_float2(r * s, im * s);
    g_a[d] = a;
    float2 p = a;
#pragma unroll
    for (int k = 0; k < LOG2C; k++) p = cmul(p, p);
    g_aC[d] = p;
}

// K1: per (b, chunk, d) local scan total with zero initial state.
__global__ void k_chunk_totals(const float* __restrict__ x,
                               const float* __restrict__ cr_in,
                               const float* __restrict__ ci_in) {
    int d     = blockIdx.x * blockDim.x + threadIdx.x;  // 0..D-1
    int chunk = blockIdx.y;
    int b     = blockIdx.z;
    float2 a = g_a[d];
    float cr = cr_in[d], ci = ci_in[d];
    const float* xp = x + ((size_t)b * L + (size_t)chunk * C) * D + d;

    float hr = 0.0f, hi = 0.0f;
#pragma unroll 8
    for (int t = 0; t < C; t++) {
        float xv = xp[(size_t)t * D];
        float nr = fmaf(a.x, hr, fmaf(-a.y, hi, cr * xv));
        float ni = fmaf(a.x, hi, fmaf( a.y, hr, ci * xv));
        hr = nr; hi = ni;
    }
    g_totals[((size_t)b * NC + chunk) * D + d] = make_float2(hr, hi);
}

// K2: per (b,d), serial carry propagation across NC chunks (tiny kernel).
__global__ void k_carries(const float* __restrict__ lcr, const float* __restrict__ lci) {
    int idx = blockIdx.x * blockDim.x + threadIdx.x;  // 0 .. B*D-1
    if (idx >= B * D) return;
    int b = idx / D, d = idx % D;
    float2 aC = g_aC[d];
    float cr = lcr[idx], ci = lci[idx];  // h[-1] = last_conv
    g_carry[((size_t)b * NC + 0) * D + d] = make_float2(cr, ci);
#pragma unroll
    for (int i = 1; i < NC; i++) {
        float2 tot = g_totals[((size_t)b * NC + (i - 1)) * D + d];
        float nr = fmaf(aC.x, cr, fmaf(-aC.y, ci, tot.x));
        float ni = fmaf(aC.x, ci, fmaf( aC.y, cr, tot.y));
        cr = nr; ci = ni;
        g_carry[((size_t)b * NC + i) * D + d] = make_float2(cr, ci);
    }
}

// K3: per (b, chunk, d) exact scan seeded with carry-in; write Re(h).
__global__ void k_scan_out(const float* __restrict__ x,
                           const float* __restrict__ cr_in,
                           const float* __restrict__ ci_in,
                           float* __restrict__ out) {
    int d     = blockIdx.x * blockDim.x + threadIdx.x;
    int chunk = blockIdx.y;
    int b     = blockIdx.z;
    float2 a = g_a[d];
    float cr = cr_in[d], ci = ci_in[d];
    size_t base = ((size_t)b * L + (size_t)chunk * C) * D + d;
    const float* xp = x + base;
    float* op = out + base;

    float2 h0 = g_carry[((size_t)b * NC + chunk) * D + d];
    float hr = h0.x, hi = h0.y;
#pragma unroll 8
    for (int t = 0; t < C; t++) {
        float xv = xp[(size_t)t * D];
        float nr = fmaf(a.x, hr, fmaf(-a.y, hi, cr * xv));
        float ni = fmaf(a.x, hi, fmaf( a.y, hr, ci * xv));
        hr = nr; hi = ni;
        op[(size_t)t * D] = hr;
    }
}

extern "C" void kernel_launch(void* const* d_in, const int* in_sizes, int n_in,
                              void* d_out, int out_size) {
    const float* x    = (const float*)d_in[0];
    const float* p_re = (const float*)d_in[1];
    const float* p_im = (const float*)d_in[2];
    const float* i_re = (const float*)d_in[3];
    const float* i_im = (const float*)d_in[4];
    const float* lc_r = (const float*)d_in[5];
    const float* lc_i = (const float*)d_in[6];
    float* out = (float*)d_out;

    // K0: precompute a, a^C
    k_precompute<<<(D + 255) / 256, 256>>>(p_re, p_im);

    // K1: local chunk totals
    {
        dim3 grid(D / 256, NC, B);
        k_chunk_totals<<<grid, 256>>>(x, i_re, i_im);
    }

    // K2: carry propagation
    k_carries<<<(B * D + 255) / 256, 256>>>(lc_r, lc_i);

    // K3: final scan + output
    {
        dim3 grid(D / 256, NC, B);
        k_scan_out<<<grid, 256>>>(x, i_re, i_im, out);
    }
}